// round 1
// baseline (speedup 1.0000x reference)
#include <cuda_runtime.h>
#include <math.h>

#define HN   12
#define TT   1024
#define DD   64
#define DINE 768
#define NBB  4
#define NTR  (NBB*TT)   // 4096 rows

#define SPAD 1026       // sS row stride (pad for bank-conflict-free + float2 align)
#define KPAD 65         // sQ/sK row stride

// Scratch (static device globals — allocation-free)
__device__ float g_q[NBB*HN*TT*DD];
__device__ float g_k[NBB*HN*TT*DD];
__device__ float g_v[NBB*HN*TT*DD];
__device__ float g_o[NTR*DINE];

// ---------------------------------------------------------------------------
// QKV projection: 36 GEMMs  C[4096,64] = X[4096,768] @ W_h[768,64]
// blockIdx.y = mat*12 + h ; blockIdx.x = 128-row tile
// ---------------------------------------------------------------------------
__global__ __launch_bounds__(256) void qkv_kernel(
    const float* __restrict__ x,
    const float* __restrict__ Wq, const float* __restrict__ Wk,
    const float* __restrict__ Wv)
{
    int mh  = blockIdx.y;
    int mat = mh / HN, h = mh % HN;
    const float* W = (mat == 0 ? Wq : mat == 1 ? Wk : Wv) + (size_t)h * DINE * DD;
    float* outp    = (mat == 0 ? g_q : mat == 1 ? g_k : g_v);
    int row0 = blockIdx.x * 128;

    __shared__ float sA[16][128];  // A transposed: [kk][row]
    __shared__ float sB[16][64];

    int tid = threadIdx.x;
    int tx = tid & 15, ty = tid >> 4;

    float acc[8][4];
#pragma unroll
    for (int i = 0; i < 8; i++)
#pragma unroll
        for (int j = 0; j < 4; j++) acc[i][j] = 0.f;

    for (int k0 = 0; k0 < DINE; k0 += 16) {
#pragma unroll
        for (int i = 0; i < 2; i++) {              // 128x16 = 512 float4
            int v = tid + 256 * i;
            int r = v >> 2, kq = v & 3;
            float4 a = *(const float4*)&x[(size_t)(row0 + r) * DINE + k0 + 4 * kq];
            sA[4*kq+0][r] = a.x; sA[4*kq+1][r] = a.y;
            sA[4*kq+2][r] = a.z; sA[4*kq+3][r] = a.w;
        }
        {
            int kk = tid >> 4, c4 = tid & 15;      // 16x64 = 256 float4
            *(float4*)&sB[kk][4*c4] = *(const float4*)&W[(size_t)(k0+kk)*DD + 4*c4];
        }
        __syncthreads();
#pragma unroll
        for (int kk = 0; kk < 16; kk++) {
            float4 a0 = *(float4*)&sA[kk][ty*8];
            float4 a1 = *(float4*)&sA[kk][ty*8+4];
            float4 b  = *(float4*)&sB[kk][tx*4];
            float av[8] = {a0.x,a0.y,a0.z,a0.w,a1.x,a1.y,a1.z,a1.w};
            float bv[4] = {b.x,b.y,b.z,b.w};
#pragma unroll
            for (int i = 0; i < 8; i++)
#pragma unroll
                for (int j = 0; j < 4; j++)
                    acc[i][j] = fmaf(av[i], bv[j], acc[i][j]);
        }
        __syncthreads();
    }
#pragma unroll
    for (int i = 0; i < 8; i++) {
        int row = row0 + ty*8 + i;
        int n = row >> 10, t = row & (TT - 1);
        float4 v = make_float4(acc[i][0], acc[i][1], acc[i][2], acc[i][3]);
        *(float4*)&outp[(size_t)((n*HN + h)*TT + t)*DD + tx*4] = v;
    }
}

// ---------------------------------------------------------------------------
// Fused attention: per block (n,h, 32-query tile).
// S tile (32x1024) lives in smem; causal mask + "==0 -> -inf"; softmax;
// attn written once to gmem; O = P @ V capped at tq0+32 keys.
// ---------------------------------------------------------------------------
__global__ __launch_bounds__(256) void attn_kernel(float* __restrict__ attn_out)
{
    extern __shared__ float sm[];
    float* sS = sm;                     // 32 * SPAD
    float* sQ = sm + 32 * SPAD;         // 32 * KPAD
    float* sK = sQ + 32 * KPAD;         // 256 * KPAD (reused for V)

    int qt = blockIdx.x, bh = blockIdx.y;
    int tq0 = qt * 32;
    const float* qp = g_q + (size_t)bh * TT * DD;
    const float* kp = g_k + (size_t)bh * TT * DD;
    const float* vp = g_v + (size_t)bh * TT * DD;

    int tid = threadIdx.x, lane = tid & 31, warp = tid >> 5;

    // Load Q tile [32 x 64]
#pragma unroll
    for (int i = 0; i < 2; i++) {
        int v = tid + 256 * i;
        int r = v >> 4, e4 = v & 15;
        float4 q4 = *(const float4*)&qp[(size_t)(tq0 + r) * DD + 4 * e4];
        float* dst = &sQ[r * KPAD + 4 * e4];
        dst[0] = q4.x; dst[1] = q4.y; dst[2] = q4.z; dst[3] = q4.w;
    }
    __syncthreads();

    // ---- S = Q @ K^T over needed key blocks (causal skip) ----
    int nkb = min(4, (tq0 + 32 + 255) >> 8);
    for (int kb = 0; kb < nkb; kb++) {
#pragma unroll
        for (int i = 0; i < 16; i++) {            // 256x64 keys
            int v = tid + 256 * i;
            int s = v >> 4, e4 = v & 15;
            float4 k4 = *(const float4*)&kp[(size_t)(kb*256 + s) * DD + 4 * e4];
            float* dst = &sK[s * KPAD + 4 * e4];
            dst[0] = k4.x; dst[1] = k4.y; dst[2] = k4.z; dst[3] = k4.w;
        }
        __syncthreads();

        float acc[4][8];
#pragma unroll
        for (int i = 0; i < 4; i++)
#pragma unroll
            for (int j = 0; j < 8; j++) acc[i][j] = 0.f;

#pragma unroll 4
        for (int e = 0; e < 64; e++) {
            float a[4], b[8];
#pragma unroll
            for (int i = 0; i < 4; i++) a[i] = sQ[(warp*4 + i) * KPAD + e];
#pragma unroll
            for (int j = 0; j < 8; j++) b[j] = sK[(lane + 32*j) * KPAD + e];
#pragma unroll
            for (int i = 0; i < 4; i++)
#pragma unroll
                for (int j = 0; j < 8; j++)
                    acc[i][j] = fmaf(a[i], b[j], acc[i][j]);
        }
#pragma unroll
        for (int i = 0; i < 4; i++)
#pragma unroll
            for (int j = 0; j < 8; j++)
                sS[(warp*4 + i) * SPAD + kb*256 + lane + 32*j] = acc[i][j];
        __syncthreads();
    }

    // ---- mask + softmax (each warp owns its 4 rows) ----
#pragma unroll
    for (int i = 0; i < 4; i++) {
        int r = warp*4 + i, tq = tq0 + r;
        float* row = &sS[r * SPAD];
        float mx = -INFINITY;
        for (int s = lane; s < TT; s += 32) {
            float vv = -INFINITY;
            if (s <= tq) { vv = row[s]; if (vv == 0.0f) vv = -INFINITY; }
            row[s] = vv;
            mx = fmaxf(mx, vv);
        }
#pragma unroll
        for (int o = 16; o > 0; o >>= 1) mx = fmaxf(mx, __shfl_xor_sync(0xffffffffu, mx, o));
        float sum = 0.f;
        for (int s = lane; s < TT; s += 32) {
            float p = expf(row[s] - mx);
            row[s] = p;
            sum += p;
        }
#pragma unroll
        for (int o = 16; o > 0; o >>= 1) sum += __shfl_xor_sync(0xffffffffu, sum, o);
        float inv = 1.f / sum;
        if (attn_out) {
            float* arow = attn_out + ((size_t)bh * TT + tq) * TT;
            for (int s = lane; s < TT; s += 32) {
                float p = row[s] * inv;
                row[s] = p;
                arow[s] = p;
            }
        } else {
            for (int s = lane; s < TT; s += 32) row[s] *= inv;
        }
    }

    // ---- O = P @ V (only keys < tq0+32 contribute) ----
    float oacc[4][2];
#pragma unroll
    for (int i = 0; i < 4; i++) { oacc[i][0] = 0.f; oacc[i][1] = 0.f; }
    int kmax = tq0 + 32;
    for (int sb = 0; sb < kmax; sb += 256) {
        __syncthreads();                           // sK free to overwrite
#pragma unroll
        for (int i = 0; i < 16; i++) {
            int v = tid + 256 * i;
            int s = v >> 4, e4 = v & 15;
            float4 v4 = *(const float4*)&vp[(size_t)(sb + s) * DD + 4 * e4];
            float* dst = &sK[s * KPAD + 4 * e4];
            dst[0] = v4.x; dst[1] = v4.y; dst[2] = v4.z; dst[3] = v4.w;
        }
        __syncthreads();                           // V loaded + softmax done
        int send = min(256, kmax - sb);
#pragma unroll 2
        for (int ss = 0; ss < send; ss += 2) {
            float b00 = sK[ss * KPAD + lane];
            float b01 = sK[ss * KPAD + lane + 32];
            float b10 = sK[(ss+1) * KPAD + lane];
            float b11 = sK[(ss+1) * KPAD + lane + 32];
#pragma unroll
            for (int i = 0; i < 4; i++) {
                float2 a2 = *(float2*)&sS[(warp*4 + i) * SPAD + sb + ss];
                oacc[i][0] = fmaf(a2.x, b00, oacc[i][0]);
                oacc[i][0] = fmaf(a2.y, b10, oacc[i][0]);
                oacc[i][1] = fmaf(a2.x, b01, oacc[i][1]);
                oacc[i][1] = fmaf(a2.y, b11, oacc[i][1]);
            }
        }
    }
    int n = bh / HN, h = bh % HN;
#pragma unroll
    for (int i = 0; i < 4; i++) {
        int t = tq0 + warp*4 + i;
        float* dst = &g_o[(size_t)(n*TT + t) * DINE + h*DD];
        dst[lane]      = oacc[i][0];
        dst[lane + 32] = oacc[i][1];
    }
}

// ---------------------------------------------------------------------------
// Output projection: out[4096,64] = g_o[4096,768] @ Wo[768,64] + bo
// ---------------------------------------------------------------------------
__global__ __launch_bounds__(256) void oproj_kernel(
    const float* __restrict__ Wo, const float* __restrict__ bo,
    float* __restrict__ out)
{
    int row0 = blockIdx.x * 64;
    __shared__ float sA[16][64];   // transposed [kk][row]
    __shared__ float sB[16][64];
    int tid = threadIdx.x, tx = tid & 15, ty = tid >> 4;

    float acc[4][4];
#pragma unroll
    for (int i = 0; i < 4; i++)
#pragma unroll
        for (int j = 0; j < 4; j++) acc[i][j] = 0.f;

    for (int k0 = 0; k0 < DINE; k0 += 16) {
        {
            int r = tid >> 2, kq = tid & 3;        // 64x16 = 256 float4
            float4 a = *(const float4*)&g_o[(size_t)(row0 + r) * DINE + k0 + 4 * kq];
            sA[4*kq+0][r] = a.x; sA[4*kq+1][r] = a.y;
            sA[4*kq+2][r] = a.z; sA[4*kq+3][r] = a.w;
        }
        {
            int kk = tid >> 4, c4 = tid & 15;
            *(float4*)&sB[kk][4*c4] = *(const float4*)&Wo[(size_t)(k0+kk)*DD + 4*c4];
        }
        __syncthreads();
#pragma unroll
        for (int kk = 0; kk < 16; kk++) {
            float4 a = *(float4*)&sA[kk][ty*4];
            float4 b = *(float4*)&sB[kk][tx*4];
            float av[4] = {a.x,a.y,a.z,a.w};
            float bv[4] = {b.x,b.y,b.z,b.w};
#pragma unroll
            for (int i = 0; i < 4; i++)
#pragma unroll
                for (int j = 0; j < 4; j++)
                    acc[i][j] = fmaf(av[i], bv[j], acc[i][j]);
        }
        __syncthreads();
    }
    float4 bias = *(const float4*)&bo[tx*4];
    float bv[4] = {bias.x, bias.y, bias.z, bias.w};
#pragma unroll
    for (int i = 0; i < 4; i++) {
        int row = row0 + ty*4 + i;
        float4 v = make_float4(acc[i][0]+bv[0], acc[i][1]+bv[1],
                               acc[i][2]+bv[2], acc[i][3]+bv[3]);
        *(float4*)&out[(size_t)row * DD + tx*4] = v;
    }
}

// ---------------------------------------------------------------------------
extern "C" void kernel_launch(void* const* d_in, const int* in_sizes, int n_in,
                              void* d_out, int out_size)
{
    const float* x  = (const float*)d_in[0];
    const float* Wq = (const float*)d_in[1];
    const float* Wk = (const float*)d_in[2];
    const float* Wv = (const float*)d_in[3];
    const float* Wo = (const float*)d_in[4];
    const float* bo = (const float*)d_in[5];
    float* out = (float*)d_out;

    const long NTD = (long)NBB * TT * DD;            // 262144
    const long ATT = (long)NBB * HN * TT * TT;       // 50331648
    float* attn = nullptr;
    if ((long)out_size >= NTD + ATT) attn = out + NTD;

    int smem = (32 * SPAD + 32 * KPAD + 256 * KPAD) * (int)sizeof(float); // 206208 B
    cudaFuncSetAttribute(attn_kernel, cudaFuncAttributeMaxDynamicSharedMemorySize, smem);

    qkv_kernel<<<dim3(32, 36), 256>>>(x, Wq, Wk, Wv);
    attn_kernel<<<dim3(32, 48), 256, smem>>>(attn);
    oproj_kernel<<<64, 256>>>(Wo, bo, out);
}